// round 3
// baseline (speedup 1.0000x reference)
#include <cuda_runtime.h>
#include <cstdint>

// Problem constants
#define NN   384
#define HH   128
#define LATD 64
#define RR   16
#define LL   3
#define TT   64
#define USs  148     // us row stride (592B = 37*16)
#define MSs  132     // m1s row stride (528B = 33*16)
#define GRID_E 148   // persistent edge CTAs (1 wave)
#define CUT2 144.0f
#define GAMMA 1.7777778f   // (16/12)^2
#define MUSTEP 0.8f        // 12/15

typedef unsigned long long u64;

// ---------------- device scratch ----------------
__device__ float g_h[NN * HH];
__device__ float g_x[NN * 3];
__device__ float g_agg[NN * HH];
__device__ float g_xupd[NN * 3];

__device__ __forceinline__ float silu_f(float v) {
    return __fdividef(v, 1.0f + __expf(-v));
}
__device__ __forceinline__ u64 pk2(float x, float y) {
    u64 r; asm("mov.b64 %0,{%1,%2};" : "=l"(r) : "f"(x), "f"(y)); return r;
}
__device__ __forceinline__ u64 fma2(u64 a, u64 b, u64 c) {
    u64 d; asm("fma.rn.f32x2 %0,%1,%2,%3;" : "=l"(d) : "l"(a), "l"(b), "l"(c)); return d;
}
__device__ __forceinline__ float2 upk(u64 a) {
    float2 f; asm("mov.b64 {%0,%1},%2;" : "=f"(f.x), "=f"(f.y) : "l"(a)); return f;
}
__device__ __forceinline__ void cpa16(float* s, const float* g) {
    unsigned sa = (unsigned)__cvta_generic_to_shared(s);
    asm volatile("cp.async.cg.shared.global [%0], [%1], 16;" :: "r"(sa), "l"(g));
}
__device__ __forceinline__ void cpa_commit() { asm volatile("cp.async.commit_group;"); }
template <int W> __device__ __forceinline__ void cpa_wait() {
    asm volatile("cp.async.wait_group %0;" :: "n"(W) : "memory");
}
__device__ __forceinline__ void stage_async(float* dst, const float* src, int nfl, int tid) {
    for (int i = tid * 4; i < nfl; i += 1024) cpa16(dst + i, src + i);
}

// ---------------- init: proj (blocks 0..383) + center (block 384) ----------------
__global__ void k_init(const float* __restrict__ z, const float* __restrict__ W,
                       const float* __restrict__ b, const float* __restrict__ anchor) {
    if (blockIdx.x < NN) {
        __shared__ float zr[LATD];
        int i = blockIdx.x, c = threadIdx.x;
        if (c < LATD) zr[c] = z[i * LATD + c];
        __syncthreads();
        float acc = b[c];
#pragma unroll 8
        for (int k = 0; k < LATD; k++) acc = fmaf(zr[k], W[k * HH + c], acc);
        g_h[i * HH + c] = acc;
    } else {
        __shared__ float part[128][3];
        __shared__ float mean[3];
        int t = threadIdx.x;
        float s0 = 0.f, s1 = 0.f, s2 = 0.f;
        for (int j = t; j < NN; j += 128) {
            s0 += anchor[j * 3 + 0]; s1 += anchor[j * 3 + 1]; s2 += anchor[j * 3 + 2];
        }
        part[t][0] = s0; part[t][1] = s1; part[t][2] = s2;
        __syncthreads();
        if (t < 3) {
            float s = 0.f;
            for (int q = 0; q < 128; q++) s += part[q][t];
            mean[t] = s / (float)NN;
        }
        __syncthreads();
        for (int j = t; j < NN; j += 128) {
            g_x[j * 3 + 0] = anchor[j * 3 + 0] - mean[0];
            g_x[j * 3 + 1] = anchor[j * 3 + 1] - mean[1];
            g_x[j * 3 + 2] = anchor[j * 3 + 2] - mean[2];
        }
    }
}

// ---------------- tile GEMM (f32x2, 4j x 8c per thread) ----------------
template <int K>
__device__ __forceinline__ void gemm2x(const float* __restrict__ u, int ustr,
                                       const float* __restrict__ w,
                                       const float* __restrict__ bias,
                                       float* __restrict__ dst, int dstr,
                                       int tid, int tc) {
    if (((tid >> 5) << 3) >= tc) return;   // warp-level tail skip
    const int cg = (tid & 15) * 8;
    const int jg = (tid >> 4) * 4;
    const u64* bp = (const u64*)(bias + cg);
    u64 b0 = bp[0], b1 = bp[1], b2 = bp[2], b3 = bp[3];
    u64 acc[4][4];
#pragma unroll
    for (int jj = 0; jj < 4; jj++) {
        acc[jj][0] = b0; acc[jj][1] = b1; acc[jj][2] = b2; acc[jj][3] = b3;
    }
    const float* u0 = u + jg * ustr;
#pragma unroll 4
    for (int k = 0; k < K; k += 2) {
        ulonglong2 w0a = *(const ulonglong2*)(w + k * HH + cg);
        ulonglong2 w0b = *(const ulonglong2*)(w + k * HH + cg + 4);
        ulonglong2 w1a = *(const ulonglong2*)(w + (k + 1) * HH + cg);
        ulonglong2 w1b = *(const ulonglong2*)(w + (k + 1) * HH + cg + 4);
#pragma unroll
        for (int jj = 0; jj < 4; jj++) {
            float2 uv = *(const float2*)(u0 + jj * ustr + k);
            u64 ua = pk2(uv.x, uv.x), ub = pk2(uv.y, uv.y);
            acc[jj][0] = fma2(ua, w0a.x, acc[jj][0]);
            acc[jj][1] = fma2(ua, w0a.y, acc[jj][1]);
            acc[jj][2] = fma2(ua, w0b.x, acc[jj][2]);
            acc[jj][3] = fma2(ua, w0b.y, acc[jj][3]);
            acc[jj][0] = fma2(ub, w1a.x, acc[jj][0]);
            acc[jj][1] = fma2(ub, w1a.y, acc[jj][1]);
            acc[jj][2] = fma2(ub, w1b.x, acc[jj][2]);
            acc[jj][3] = fma2(ub, w1b.y, acc[jj][3]);
        }
    }
#pragma unroll
    for (int jj = 0; jj < 4; jj++) {
        float* d = dst + (jg + jj) * dstr + cg;
        float2 t; float4 o0, o1;
        t = upk(acc[jj][0]); o0.x = silu_f(t.x); o0.y = silu_f(t.y);
        t = upk(acc[jj][1]); o0.z = silu_f(t.x); o0.w = silu_f(t.y);
        t = upk(acc[jj][2]); o1.x = silu_f(t.x); o1.y = silu_f(t.y);
        t = upk(acc[jj][3]); o1.z = silu_f(t.x); o1.w = silu_f(t.y);
        *(float4*)(d) = o0; *(float4*)(d + 4) = o1;
    }
}

// ---------------- persistent edge kernel ----------------
// smem floats: eW1s 18432 | wb2 16384 | us 9472 | m1s 8448 | xs 1152 | 6*HH | dlist 384
//              cont 192 | xacc 4 | ints 404
#define SM_FLOATS (144*HH + HH*HH + TT*USs + TT*MSs + NN*3 + 6*HH + NN + TT*3 + 4)
#define SM_INTS   (NN + 8 + 8 + 4)
#define SMEM_EDGE ((SM_FLOATS + SM_INTS) * 4)

__global__ __launch_bounds__(256, 1) void k_edge(
    const float* __restrict__ eW1, const float* __restrict__ eb1,
    const float* __restrict__ eW2, const float* __restrict__ eb2,
    const float* __restrict__ cW1, const float* __restrict__ cb1,
    const float* __restrict__ cW2, int l) {
    extern __shared__ float sm[];
    float* eW1s  = sm;                   // 144*HH  resident
    float* wb2   = eW1s + 144 * HH;      // HH*HH   (eW2 / cW1 alternating)
    float* us    = wb2 + HH * HH;        // TT*USs
    float* m1s   = us + TT * USs;        // TT*MSs
    float* xs    = m1s + TT * MSs;       // NN*3
    float* hi_s  = xs + NN * 3;          // HH
    float* base1 = hi_s + HH;            // HH
    float* eb2s  = base1 + HH;           // HH
    float* cb1s  = eb2s + HH;            // HH
    float* cW2s  = cb1s + HH;            // HH
    float* aggs  = cW2s + HH;            // HH
    float* dlist = aggs + HH;            // NN
    float* cont  = dlist + NN;           // TT*3
    float* xacc  = cont + TT * 3;        // 4
    int* nbr   = (int*)(xacc + 4);       // NN
    int* wcnt  = nbr + NN;               // 8
    int* wbase = wcnt + 8;               // 8
    int* misc  = wbase + 8;              // 4

    const int tid = threadIdx.x;
    const int lane = tid & 31, wrp = tid >> 5;

    const float* eW1hj = eW1 + ((size_t)l * 272 + HH) * HH;
    const float* eW2l  = eW2 + (size_t)l * HH * HH;
    const float* cW1l  = cW1 + (size_t)l * HH * HH;

    // resident eW1 (hj+rbf part) — staged once
    stage_async(eW1s, eW1hj, 144 * HH, tid);
    cpa_commit();

    for (int t = tid; t < NN * 3; t += 256) xs[t] = g_x[t];
    if (tid < HH) {
        eb2s[tid] = eb2[l * HH + tid];
        cb1s[tid] = cb1[l * HH + tid];
        cW2s[tid] = cW2[l * HH + tid];
    }
    __syncthreads();

    for (int r = blockIdx.x; r < NN; r += GRID_E) {
        if (tid < HH) { hi_s[tid] = g_h[r * HH + tid]; aggs[tid] = 0.f; }
        if (tid == 0) misc[0] = 0;
        if (tid < 3) xacc[tid] = 0.f;
        __syncthreads();

        const float xi0 = xs[r * 3 + 0], xi1 = xs[r * 3 + 1], xi2 = xs[r * 3 + 2];

        // base1 = eb1 + hi @ eW1[0:128]  (L2-direct, 4-way acc)
        if (tid < HH) {
            const float* Wl = eW1 + (size_t)l * 272 * HH + tid;
            float a0 = __ldg(eb1 + l * HH + tid), a1 = 0.f, a2 = 0.f, a3 = 0.f;
#pragma unroll 4
            for (int k = 0; k < HH; k += 4) {
                a0 = fmaf(hi_s[k + 0], __ldg(Wl + (k + 0) * HH), a0);
                a1 = fmaf(hi_s[k + 1], __ldg(Wl + (k + 1) * HH), a1);
                a2 = fmaf(hi_s[k + 2], __ldg(Wl + (k + 2) * HH), a2);
                a3 = fmaf(hi_s[k + 3], __ldg(Wl + (k + 3) * HH), a3);
            }
            base1[tid] = (a0 + a1) + (a2 + a3);
        }

        // deterministic ordered neighbor compaction
        for (int base = 0; base < NN; base += 256) {
            int j = base + tid;
            bool p = false;
            float d2 = 0.f;
            if (j < NN && j != r) {
                float dx = xi0 - xs[j * 3 + 0];
                float dy = xi1 - xs[j * 3 + 1];
                float dz = xi2 - xs[j * 3 + 2];
                d2 = dx * dx + dy * dy + dz * dz;
                p = (d2 < CUT2) || (j == r - 1) || (j == r + 1);
            }
            unsigned bal = __ballot_sync(0xffffffffu, p);
            if (lane == 0) wcnt[wrp] = __popc(bal);
            __syncthreads();
            if (tid == 0) {
                int run = misc[0];
                for (int q = 0; q < 8; q++) { wbase[q] = run; run += wcnt[q]; }
                misc[0] = run;
            }
            __syncthreads();
            if (p) {
                int pos = wbase[wrp] + __popc(bal & ((1u << lane) - 1u));
                nbr[pos] = j;
                dlist[pos] = sqrtf(d2);
            }
            __syncthreads();
        }
        const int cnt = misc[0];

        for (int t0 = 0; t0 < cnt; t0 += TT) {
            const int tc = min(TT, cnt - t0);
            const int tcr8 = (tc + 7) & ~7;

            stage_async(wb2, eW2l, HH * HH, tid);   // prefetch eW2 (overlaps gemm1)
            cpa_commit();

            // stage [hj | rbf] tile
            for (int idx = tid; idx < tcr8 * (HH / 4); idx += 256) {
                int jj = idx >> 5, c4 = (idx & 31) << 2;
                float4 v = make_float4(0.f, 0.f, 0.f, 0.f);
                if (jj < tc) v = *(const float4*)(g_h + nbr[t0 + jj] * HH + c4);
                *(float4*)(us + jj * USs + c4) = v;
            }
            for (int idx = tid; idx < tcr8 * RR; idx += 256) {
                int jj = idx >> 4, rb = idx & 15;
                float v = 0.f;
                if (jj < tc) {
                    float dd = dlist[t0 + jj] - MUSTEP * (float)rb;
                    v = __expf(-GAMMA * dd * dd);
                }
                us[jj * USs + HH + rb] = v;
            }
            cpa_wait<1>();       // eW1 resident (no-op after first tile)
            __syncthreads();

            gemm2x<144>(us, USs, eW1s, base1, m1s, MSs, tid, tc);   // m1

            cpa_wait<0>();       // eW2 staged
            __syncthreads();

            gemm2x<128>(m1s, MSs, wb2, eb2s, us, MSs, tid, tc);     // m -> us
            __syncthreads();     // gemm2 done; wb2 free

            stage_async(wb2, cW1l, HH * HH, tid);   // prefetch cW1
            cpa_commit();

            if (tid < HH) {      // agg (deterministic serial) overlaps cW1 stage
                float s = 0.f;
                for (int jj = 0; jj < tc; jj++) s += us[jj * MSs + tid];
                aggs[tid] += s;
            }
            cpa_wait<0>();
            __syncthreads();

            gemm2x<128>(us, MSs, wb2, cb1s, m1s, MSs, tid, tc);     // c1
            __syncthreads();

            if (tid < tc) {
                const float* mr = m1s + tid * MSs;
                float s = 0.f;
#pragma unroll 8
                for (int c = 0; c < HH; c++) s = fmaf(mr[c], cW2s[c], s);
                int j = nbr[t0 + tid];
                cont[tid * 3 + 0] = (xi0 - xs[j * 3 + 0]) * s;
                cont[tid * 3 + 1] = (xi1 - xs[j * 3 + 1]) * s;
                cont[tid * 3 + 2] = (xi2 - xs[j * 3 + 2]) * s;
            }
            __syncthreads();
            if (tid < 3) {
                float s = xacc[tid];
                for (int jj = 0; jj < tc; jj++) s += cont[jj * 3 + tid];
                xacc[tid] = s;
            }
            __syncthreads();
        }

        if (tid < HH) g_agg[r * HH + tid] = aggs[tid];
        if (tid < 3) g_xupd[r * 3 + tid] = xacc[tid];
        __syncthreads();
    }
}

// ---------------- k_node: split-K over warps, L2-direct weights ----------------
// grid = NN/8 = 48 CTAs, 256 threads. warp w owns k-slice [w*16, w*16+16).
__global__ __launch_bounds__(256, 4) void k_node(
    const float* __restrict__ nW1, const float* __restrict__ nb1,
    const float* __restrict__ nW2, const float* __restrict__ nb2,
    int l, float* __restrict__ out, int last) {
    __shared__ __align__(16) float hs[8 * HH];
    __shared__ __align__(16) float as_[8 * HH];
    __shared__ __align__(16) float n1s[8 * HH];
    __shared__ __align__(16) float part[64 * HH];   // [warp][row][col]
    __shared__ __align__(16) float b1s[HH], b2s[HH];

    const int tid = threadIdx.x;
    const int w = tid >> 5, lane = tid & 31;
    const int c4 = lane * 4;
    const int r0 = blockIdx.x * 8;
    const int kb = w * 16;

    // coord update (independent of h path) — do first
    if (tid < 24) {
        int rr = tid / 3, cc = tid - rr * 3;
        float v = g_x[(r0 + rr) * 3 + cc] + g_xupd[(r0 + rr) * 3 + cc];
        g_x[(r0 + rr) * 3 + cc] = v;
        if (last) out[(r0 + rr) * 3 + cc] = v;
    }
    {
        int idx = tid;  // 256 float4 = 8*128 floats
        *(float4*)(hs + idx * 4)  = *(const float4*)(g_h + r0 * HH + idx * 4);
        *(float4*)(as_ + idx * 4) = *(const float4*)(g_agg + r0 * HH + idx * 4);
    }
    if (tid < HH) { b1s[tid] = nb1[l * HH + tid]; b2s[tid] = nb2[l * HH + tid]; }
    __syncthreads();

    const float* W1 = nW1 + (size_t)l * 2 * HH * HH;
    const float* W2 = nW2 + (size_t)l * HH * HH;

    // phase 1: n1 = silu(nb1 + [h|agg] @ W1)
    {
        u64 acc[8][2];
#pragma unroll
        for (int rr = 0; rr < 8; rr++) { acc[rr][0] = 0; acc[rr][1] = 0; }
#pragma unroll 2
        for (int kk = 0; kk < 16; kk++) {
            int k = kb + kk;
            float4 wv = __ldg((const float4*)(W1 + (size_t)k * HH + c4));
            u64 w01 = pk2(wv.x, wv.y), w23 = pk2(wv.z, wv.w);
#pragma unroll
            for (int rr = 0; rr < 8; rr++) {
                float hb = hs[rr * HH + k];
                u64 hbb = pk2(hb, hb);
                acc[rr][0] = fma2(hbb, w01, acc[rr][0]);
                acc[rr][1] = fma2(hbb, w23, acc[rr][1]);
            }
            float4 wv2 = __ldg((const float4*)(W1 + (size_t)(HH + k) * HH + c4));
            u64 v01 = pk2(wv2.x, wv2.y), v23 = pk2(wv2.z, wv2.w);
#pragma unroll
            for (int rr = 0; rr < 8; rr++) {
                float ab = as_[rr * HH + k];
                u64 abb = pk2(ab, ab);
                acc[rr][0] = fma2(abb, v01, acc[rr][0]);
                acc[rr][1] = fma2(abb, v23, acc[rr][1]);
            }
        }
#pragma unroll
        for (int rr = 0; rr < 8; rr++) {
            float2 t0 = upk(acc[rr][0]), t1 = upk(acc[rr][1]);
            *(float4*)(part + (w * 8 + rr) * HH + c4) = make_float4(t0.x, t0.y, t1.x, t1.y);
        }
    }
    __syncthreads();
    {
        int r = tid >> 5;
        float4 s = *(const float4*)(b1s + c4);
#pragma unroll
        for (int q = 0; q < 8; q++) {
            float4 p = *(const float4*)(part + (q * 8 + r) * HH + c4);
            s.x += p.x; s.y += p.y; s.z += p.z; s.w += p.w;
        }
        n1s[r * HH + c4 + 0] = silu_f(s.x);
        n1s[r * HH + c4 + 1] = silu_f(s.y);
        n1s[r * HH + c4 + 2] = silu_f(s.z);
        n1s[r * HH + c4 + 3] = silu_f(s.w);
    }
    __syncthreads();

    // phase 2: h' = h + nb2 + n1 @ W2
    {
        u64 acc[8][2];
#pragma unroll
        for (int rr = 0; rr < 8; rr++) { acc[rr][0] = 0; acc[rr][1] = 0; }
#pragma unroll 2
        for (int kk = 0; kk < 16; kk++) {
            int k = kb + kk;
            float4 wv = __ldg((const float4*)(W2 + (size_t)k * HH + c4));
            u64 w01 = pk2(wv.x, wv.y), w23 = pk2(wv.z, wv.w);
#pragma unroll
            for (int rr = 0; rr < 8; rr++) {
                float nb = n1s[rr * HH + k];
                u64 nbb = pk2(nb, nb);
                acc[rr][0] = fma2(nbb, w01, acc[rr][0]);
                acc[rr][1] = fma2(nbb, w23, acc[rr][1]);
            }
        }
#pragma unroll
        for (int rr = 0; rr < 8; rr++) {
            float2 t0 = upk(acc[rr][0]), t1 = upk(acc[rr][1]);
            *(float4*)(part + (w * 8 + rr) * HH + c4) = make_float4(t0.x, t0.y, t1.x, t1.y);
        }
    }
    __syncthreads();
    {
        int r = tid >> 5;
        float4 s = *(const float4*)(b2s + c4);
#pragma unroll
        for (int q = 0; q < 8; q++) {
            float4 p = *(const float4*)(part + (q * 8 + r) * HH + c4);
            s.x += p.x; s.y += p.y; s.z += p.z; s.w += p.w;
        }
        float4 h0 = *(const float4*)(hs + r * HH + c4);
        s.x += h0.x; s.y += h0.y; s.z += h0.z; s.w += h0.w;
        *(float4*)(g_h + (r0 + r) * HH + c4) = s;
    }
}

// ---------------- launch ----------------
extern "C" void kernel_launch(void* const* d_in, const int* in_sizes, int n_in,
                              void* d_out, int out_size) {
    const float* z      = (const float*)d_in[0];
    const float* anchor = (const float*)d_in[1];
    const float* proj_W = (const float*)d_in[2];
    const float* proj_b = (const float*)d_in[3];
    const float* eW1    = (const float*)d_in[4];
    const float* eb1    = (const float*)d_in[5];
    const float* eW2    = (const float*)d_in[6];
    const float* eb2    = (const float*)d_in[7];
    const float* nW1    = (const float*)d_in[8];
    const float* nb1    = (const float*)d_in[9];
    const float* nW2    = (const float*)d_in[10];
    const float* nb2    = (const float*)d_in[11];
    const float* cW1    = (const float*)d_in[12];
    const float* cb1    = (const float*)d_in[13];
    const float* cW2    = (const float*)d_in[14];

    cudaFuncSetAttribute(k_edge, cudaFuncAttributeMaxDynamicSharedMemorySize, SMEM_EDGE);

    k_init<<<NN + 1, 128>>>(z, proj_W, proj_b, anchor);
    for (int l = 0; l < LL; l++) {
        k_edge<<<GRID_E, 256, SMEM_EDGE>>>(eW1, eb1, eW2, eb2, cW1, cb1, cW2, l);
        k_node<<<NN / 8, 256>>>(nW1, nb1, nW2, nb2, l, (float*)d_out, l == LL - 1);
    }
}